// round 6
// baseline (speedup 1.0000x reference)
#include <cuda_runtime.h>
#include <math.h>

// Problem constants
#define NN     512
#define HID    1024
#define OUTD   131328          // N + N*(N-1)/2
#define OUT4   (OUTD / 4)      // 32832 float4 columns
#define SPLITK 8
#define JCH    (HID / SPLITK)  // 128 rows of Wo per k-chunk
#define MB     128             // blocks in fused MLP kernel

// Device scratch (no allocation allowed). Referenced ONLY in device code.
__device__ float g_hbuf[2][HID];         // h0, h1
__device__ float g_h2[HID];              // final tanh output of layer 2
__device__ float g_part[SPLITK][OUTD];   // split-K partial sums of big GEMV
__device__ float g_L[NN * NN];

// ---------------------------------------------------------------------------
// Software grid barrier (sense-reversal). Safe when all participating blocks
// are co-resident. Counter self-resets; generation is monotonic across graph
// replays (state evolves, outputs deterministic).
// ---------------------------------------------------------------------------
__device__ unsigned g_bar_ctr = 0;
__device__ volatile unsigned g_bar_gen = 0;

__device__ __forceinline__ void grid_barrier(unsigned nblocks) {
    __threadfence();
    __syncthreads();
    if (threadIdx.x == 0) {
        unsigned gen = g_bar_gen;
        if (atomicAdd(&g_bar_ctr, 1) == nblocks - 1) {
            g_bar_ctr = 0;
            __threadfence();
            g_bar_gen = gen + 1;
        } else {
            while (g_bar_gen == gen) __nanosleep(64);
        }
    }
    __syncthreads();
}

// ---------------------------------------------------------------------------
// Fused 3-layer MLP. grid = (MB=128), block = 256.
// Block b owns output columns j = 8b..8b+7 of every layer (complete columns,
// no cross-block reduction). Thread (slice = t>>3, colq = t&7): slice covers
// IN/32 input rows. Grid barrier between layers.
// ---------------------------------------------------------------------------
__device__ __forceinline__ void mlp_phase_ext(
    const float* __restrict__ x, const float* __restrict__ W,
    const float* __restrict__ b, float* __restrict__ out,
    float sh[32][8], int IN) {
    const int t     = threadIdx.x;
    const int colq  = t & 7;
    const int slice = t >> 3;
    const int j     = blockIdx.x * 8 + colq;
    const int CH    = IN / 32;
    const int i0    = slice * CH;

    float acc = 0.f;
    for (int i = 0; i < CH; ++i) {
        acc += x[i0 + i] * __ldg(&W[(size_t)(i0 + i) * 1024 + j]);
    }
    sh[slice][colq] = acc;
    __syncthreads();
    if (t < 8) {
        float s = 0.f;
#pragma unroll
        for (int q = 0; q < 32; ++q) s += sh[q][t];
        out[blockIdx.x * 8 + t] = tanhf(s + __ldg(&b[blockIdx.x * 8 + t]));
    }
}

__global__ void mlp_all(const float* __restrict__ x,
                        const float* __restrict__ W0, const float* __restrict__ b0,
                        const float* __restrict__ W1, const float* __restrict__ b1,
                        const float* __restrict__ W2, const float* __restrict__ b2) {
    __shared__ float sh[32][8];
    __shared__ float xs[HID];

    // phase 0: IN=512, x external
    for (int t = threadIdx.x; t < 512; t += 256) xs[t] = x[t];
    __syncthreads();
    mlp_phase_ext(xs, W0, b0, g_hbuf[0], sh, 512);
    grid_barrier(MB);

    // phase 1: IN=1024, src = g_hbuf[0]
    for (int t = threadIdx.x; t < HID; t += 256) xs[t] = g_hbuf[0][t];
    __syncthreads();
    mlp_phase_ext(xs, W1, b1, g_hbuf[1], sh, 1024);
    grid_barrier(MB);

    // phase 2: IN=1024, src = g_hbuf[1]
    for (int t = threadIdx.x; t < HID; t += 256) xs[t] = g_hbuf[1][t];
    __syncthreads();
    mlp_phase_ext(xs, W2, b2, g_h2, sh, 1024);
}

// ---------------------------------------------------------------------------
// Big GEMV, split-K: part[chunk][k] = sum_{j in chunk} h2[j] * Wo[j][k]
// grid = (129, SPLITK), block = 256. Wo is read once -> streaming loads.
// ---------------------------------------------------------------------------
__global__ void gemv_out(const float* __restrict__ Wo) {
    const int chunk = blockIdx.y;

    __shared__ float hs[JCH];
    if (threadIdx.x < JCH) hs[threadIdx.x] = g_h2[chunk * JCH + threadIdx.x];
    __syncthreads();

    const int k4 = blockIdx.x * blockDim.x + threadIdx.x;
    if (k4 >= OUT4) return;

    const float4* W4 = (const float4*)Wo + (size_t)chunk * JCH * OUT4;
    float ax = 0.f, ay = 0.f, az = 0.f, aw = 0.f;

#pragma unroll 8
    for (int j = 0; j < JCH; ++j) {
        float4 wv = __ldcs(&W4[(size_t)j * OUT4 + k4]);   // streaming: read-once
        float  hj = hs[j];
        ax += hj * wv.x;
        ay += hj * wv.y;
        az += hj * wv.z;
        aw += hj * wv.w;
    }

    float4 r; r.x = ax; r.y = ay; r.z = az; r.w = aw;
    ((float4*)g_part[chunk])[k4] = r;
}

// ---------------------------------------------------------------------------
// Fused build_L + D = L*L^T.
// Phase A: all 256 blocks grid-stride build L (split-K reduce + bias + exp).
// Grid barrier(256). Phase B: lower-triangle tiles do the GEMM (triangular-k),
// upper tiles exit. 32x32 tiles, 4x4 microtiles, 2-way k-split per block.
// ---------------------------------------------------------------------------
__global__ void buildL_gemm(const float* __restrict__ bo, float* __restrict__ D) {
    const int bi = blockIdx.y;
    const int bj = blockIdx.x;

    // ---- Phase A: build L ----
    {
        const int nthr = 256 * 128;
        int idx = (blockIdx.y * 16 + blockIdx.x) * 128 + threadIdx.x;
#pragma unroll
        for (int rep = 0; rep < (NN * NN) / (256 * 128); ++rep, idx += nthr) {
            const int r = idx >> 9;
            const int c = idx & 511;
            float v;
            if (c > r) {
                v = 0.f;
            } else {
                const int k = (c < r) ? (NN + (r * (r - 1)) / 2 + c) : r;
                float s = __ldg(&bo[k]);
#pragma unroll
                for (int q = 0; q < SPLITK; ++q) s += g_part[q][k];
                v = (c < r) ? s : expf(s);
            }
            g_L[idx] = v;
        }
    }
    grid_barrier(256);

    if (bj > bi) return;

    // ---- Phase B: GEMM ----
    __shared__ float As[64][36];   // As[kk][row]
    __shared__ float Bs[64][36];   // Bs[kk][col]
    __shared__ float red[64][16];

    const int tid  = threadIdx.x;        // 0..127
    const int grp  = tid >> 6;            // 0 or 1
    const int id64 = tid & 63;
    const int tx   = id64 & 7;
    const int ty   = id64 >> 3;

    const int lr = tid >> 2;
    const int lc = (tid & 3) * 16;

    float acc[4][4];
#pragma unroll
    for (int i = 0; i < 4; ++i)
#pragma unroll
        for (int j = 0; j < 4; ++j) acc[i][j] = 0.f;

    const int nslab = (bj >> 1) + 1;      // k <= bj*32+31 (L triangular)

    for (int s = 0; s < nslab; ++s) {
        const int k0 = s * 64;
#pragma unroll
        for (int q = 0; q < 4; ++q) {
            float4 av = *(const float4*)&g_L[(size_t)(bi * 32 + lr) * NN + k0 + lc + 4 * q];
            float4 bv = *(const float4*)&g_L[(size_t)(bj * 32 + lr) * NN + k0 + lc + 4 * q];
            const int c = lc + 4 * q;
            As[c][lr] = av.x; As[c + 1][lr] = av.y; As[c + 2][lr] = av.z; As[c + 3][lr] = av.w;
            Bs[c][lr] = bv.x; Bs[c + 1][lr] = bv.y; Bs[c + 2][lr] = bv.z; Bs[c + 3][lr] = bv.w;
        }
        __syncthreads();

        const int kb = grp * 32;
#pragma unroll
        for (int kk = 0; kk < 32; ++kk) {
            float4 a = *(const float4*)&As[kb + kk][ty * 4];
            float4 b = *(const float4*)&Bs[kb + kk][tx * 4];
            acc[0][0] += a.x * b.x; acc[0][1] += a.x * b.y; acc[0][2] += a.x * b.z; acc[0][3] += a.x * b.w;
            acc[1][0] += a.y * b.x; acc[1][1] += a.y * b.y; acc[1][2] += a.y * b.z; acc[1][3] += a.y * b.w;
            acc[2][0] += a.z * b.x; acc[2][1] += a.z * b.y; acc[2][2] += a.z * b.z; acc[2][3] += a.z * b.w;
            acc[3][0] += a.w * b.x; acc[3][1] += a.w * b.y; acc[3][2] += a.w * b.z; acc[3][3] += a.w * b.w;
        }
        __syncthreads();
    }

    if (grp == 1) {
#pragma unroll
        for (int i = 0; i < 4; ++i)
#pragma unroll
            for (int j = 0; j < 4; ++j) red[id64][i * 4 + j] = acc[i][j];
    }
    __syncthreads();
    if (grp == 0) {
#pragma unroll
        for (int i = 0; i < 4; ++i)
#pragma unroll
            for (int j = 0; j < 4; ++j) acc[i][j] += red[id64][i * 4 + j];

        const int R = bi * 32 + ty * 4;
        const int C = bj * 32 + tx * 4;
#pragma unroll
        for (int i = 0; i < 4; ++i) {
            float4 v; v.x = acc[i][0]; v.y = acc[i][1]; v.z = acc[i][2]; v.w = acc[i][3];
            *(float4*)&D[(size_t)(R + i) * NN + C] = v;
        }
        if (bi != bj) {   // mirror (D symmetric)
#pragma unroll
            for (int j = 0; j < 4; ++j) {
                float4 v; v.x = acc[0][j]; v.y = acc[1][j]; v.z = acc[2][j]; v.w = acc[3][j];
                *(float4*)&D[(size_t)(C + j) * NN + R] = v;
            }
        }
    }
}

// ---------------------------------------------------------------------------
extern "C" void kernel_launch(void* const* d_in, const int* in_sizes, int n_in,
                              void* d_out, int out_size) {
    const float* input = (const float*)d_in[0];
    const float* W0    = (const float*)d_in[1];
    const float* b0    = (const float*)d_in[2];
    const float* W1    = (const float*)d_in[3];
    const float* b1    = (const float*)d_in[4];
    const float* W2    = (const float*)d_in[5];
    const float* b2    = (const float*)d_in[6];
    const float* Wo    = (const float*)d_in[7];
    const float* bo    = (const float*)d_in[8];
    float* out = (float*)d_out;

    // Fused 3-layer MLP (single launch, grid barriers between layers)
    mlp_all<<<MB, 256>>>(input, W0, b0, W1, b1, W2, b2);

    // Dominant GEMV over Wo (537 MB stream)
    dim3 gv((OUT4 + 255) / 256, SPLITK);
    gemv_out<<<gv, 256>>>(Wo);

    // Fused L assembly + D = L L^T
    dim3 g(16, 16);
    buildL_gemm<<<g, 128>>>(bo, out);
}

// round 7
// speedup vs baseline: 1.0405x; 1.0405x over previous
#include <cuda_runtime.h>
#include <math.h>

// Problem constants
#define NN     512
#define HID    1024
#define OUTD   131328          // N + N*(N-1)/2
#define OUT4   (OUTD / 4)      // 32832 float4 columns
#define SPLITK 8
#define JCH    (HID / SPLITK)  // 128 rows of Wo per k-chunk
#define SI     4               // i-splits in fused MLP
#define MB     128             // blocks in fused MLP kernel (32 colgroups x SI)
#define GB     136             // lower-triangle tile count for gemm (16*17/2)

// Device scratch (no allocation allowed). Referenced ONLY in device code.
__device__ float g_hp[3][SI][HID];       // per-layer split-i partials (pre-bias/tanh)
__device__ float g_part[SPLITK][OUTD];   // split-K partial sums of big GEMV
__device__ float g_L[NN * NN];

// ---------------------------------------------------------------------------
// Software grid barrier (sense-reversal). Safe when all participating blocks
// are co-resident (MB=128 and GB=136 are both <= 148 SMs, 1 CTA/SM).
// Counter self-resets; generation is monotonic across graph replays.
// ---------------------------------------------------------------------------
__device__ unsigned g_bar_ctr = 0;
__device__ volatile unsigned g_bar_gen = 0;

__device__ __forceinline__ void grid_barrier(unsigned nblocks) {
    __threadfence();
    __syncthreads();
    if (threadIdx.x == 0) {
        unsigned gen = g_bar_gen;
        if (atomicAdd(&g_bar_ctr, 1) == nblocks - 1) {
            g_bar_ctr = 0;
            __threadfence();
            g_bar_gen = gen + 1;
        } else {
            while (g_bar_gen == gen) __nanosleep(32);
        }
    }
    __syncthreads();
}

// ---------------------------------------------------------------------------
// Fused 3-layer MLP, coalesced split-i layout.
// grid = 128 blocks = (32 column-groups) x (SI=4 i-splits), block = 256.
// Block (cg, isp): partial[layer][isp][cg*32+lane] over i in isp's slice.
// Warp lanes map to 32 CONSECUTIVE columns -> one 128B line per W row.
// Consumer phase fuses x = tanh(b_prev + sum_q partial_q).
// ---------------------------------------------------------------------------
template <int IN>
__device__ __forceinline__ void mlp_partial(
    const float* __restrict__ xs,     // staged input slice (CHUNK floats)
    const float* __restrict__ W,      // [IN,1024] row-major
    int cg, int isp, float* __restrict__ outp, float sh[8][32]) {
    const int CHUNK = IN / SI;
    const int CH    = CHUNK / 8;
    const int lane  = threadIdx.x & 31;
    const int w     = threadIdx.x >> 5;
    const int j     = cg * 32 + lane;
    const int base  = isp * CHUNK;
    const int i0    = w * CH;

    float acc = 0.f;
#pragma unroll
    for (int i = 0; i < CH; ++i) {
        acc += xs[i0 + i] * __ldg(&W[(size_t)(base + i0 + i) * 1024 + j]);
    }
    sh[w][lane] = acc;
    __syncthreads();
    if (w == 0) {
        float s = 0.f;
#pragma unroll
        for (int q = 0; q < 8; ++q) s += sh[q][lane];
        outp[j] = s;
    }
    __syncthreads();
}

__global__ void mlp_all(const float* __restrict__ x,
                        const float* __restrict__ W0, const float* __restrict__ b0,
                        const float* __restrict__ W1, const float* __restrict__ b1,
                        const float* __restrict__ W2) {
    __shared__ float sh[8][32];
    __shared__ float xs[HID / SI];

    const int cg  = blockIdx.x & 31;
    const int isp = blockIdx.x >> 5;

    // ---- layer 0: IN=512, raw external input ----
    {
        const int CHUNK = 512 / SI;
        for (int t = threadIdx.x; t < CHUNK; t += 256) xs[t] = x[isp * CHUNK + t];
        __syncthreads();
        mlp_partial<512>(xs, W0, cg, isp, g_hp[0][isp], sh);
    }
    grid_barrier(MB);

    // ---- layer 1: IN=1024, x = tanh(b0 + sum partials) ----
    {
        const int CHUNK = HID / SI;
        for (int t = threadIdx.x; t < CHUNK; t += 256) {
            const int g = isp * CHUNK + t;
            float s = __ldg(&b0[g]);
#pragma unroll
            for (int q = 0; q < SI; ++q) s += g_hp[0][q][g];
            xs[t] = tanhf(s);
        }
        __syncthreads();
        mlp_partial<1024>(xs, W1, cg, isp, g_hp[1][isp], sh);
    }
    grid_barrier(MB);

    // ---- layer 2: IN=1024, x = tanh(b1 + sum partials) ----
    {
        const int CHUNK = HID / SI;
        for (int t = threadIdx.x; t < CHUNK; t += 256) {
            const int g = isp * CHUNK + t;
            float s = __ldg(&b1[g]);
#pragma unroll
            for (int q = 0; q < SI; ++q) s += g_hp[1][q][g];
            xs[t] = tanhf(s);
        }
        __syncthreads();
        mlp_partial<1024>(xs, W2, cg, isp, g_hp[2][isp], sh);
    }
    // final bias+tanh fused into gemv_out's staging
}

// ---------------------------------------------------------------------------
// Big GEMV, split-K: part[chunk][k] = sum_{j in chunk} h2[j] * Wo[j][k]
// h2 = tanh(b2 + sum_q g_hp[2][q][:]) fused at staging.
// grid = (129, SPLITK), block = 256. Wo read once -> streaming loads.
// ---------------------------------------------------------------------------
__global__ void gemv_out(const float* __restrict__ Wo,
                         const float* __restrict__ b2) {
    const int chunk = blockIdx.y;

    __shared__ float hs[JCH];
    if (threadIdx.x < JCH) {
        const int t = chunk * JCH + threadIdx.x;
        float s = __ldg(&b2[t]);
#pragma unroll
        for (int q = 0; q < SI; ++q) s += g_hp[2][q][t];
        hs[threadIdx.x] = tanhf(s);
    }
    __syncthreads();

    const int k4 = blockIdx.x * blockDim.x + threadIdx.x;
    if (k4 >= OUT4) return;

    const float4* W4 = (const float4*)Wo + (size_t)chunk * JCH * OUT4;
    float ax = 0.f, ay = 0.f, az = 0.f, aw = 0.f;

#pragma unroll 8
    for (int j = 0; j < JCH; ++j) {
        float4 wv = __ldcs(&W4[(size_t)j * OUT4 + k4]);
        float  hj = hs[j];
        ax += hj * wv.x;
        ay += hj * wv.y;
        az += hj * wv.z;
        aw += hj * wv.w;
    }

    float4 r; r.x = ax; r.y = ay; r.z = az; r.w = aw;
    ((float4*)g_part[chunk])[k4] = r;
}

// ---------------------------------------------------------------------------
// Fused build_L + D = L*L^T. grid = GB=136 blocks (lower-triangle tiles only),
// block = 128. Phase A: grid-stride build L. Barrier(136). Phase B: GEMM with
// triangular-k; every block has real work.
// ---------------------------------------------------------------------------
__global__ void buildL_gemm(const float* __restrict__ bo, float* __restrict__ D) {
    // linear block id -> (bi, bj), bj <= bi
    const int b = blockIdx.x;
    int bi = (int)((sqrtf(8.f * b + 1.f) - 1.f) * 0.5f);
    while ((bi + 1) * (bi + 2) / 2 <= b) ++bi;
    while (bi * (bi + 1) / 2 > b) --bi;
    const int bj = b - bi * (bi + 1) / 2;

    // ---- Phase A: build L ----
    {
        const int T = GB * 128;
        for (int idx = b * 128 + threadIdx.x; idx < NN * NN; idx += T) {
            const int r = idx >> 9;
            const int c = idx & 511;
            float v;
            if (c > r) {
                v = 0.f;
            } else {
                const int k = (c < r) ? (NN + (r * (r - 1)) / 2 + c) : r;
                float s = __ldg(&bo[k]);
#pragma unroll
                for (int q = 0; q < SPLITK; ++q) s += g_part[q][k];
                v = (c < r) ? s : expf(s);
            }
            g_L[idx] = v;
        }
    }
    grid_barrier(GB);

    // ---- Phase B: GEMM ----
    __shared__ float As[64][36];   // As[kk][row]
    __shared__ float Bs[64][36];   // Bs[kk][col]
    __shared__ float red[64][16];

    const int tid  = threadIdx.x;        // 0..127
    const int grp  = tid >> 6;            // 0 or 1
    const int id64 = tid & 63;
    const int tx   = id64 & 7;
    const int ty   = id64 >> 3;

    const int lr = tid >> 2;
    const int lc = (tid & 3) * 16;

    float acc[4][4];
#pragma unroll
    for (int i = 0; i < 4; ++i)
#pragma unroll
        for (int j = 0; j < 4; ++j) acc[i][j] = 0.f;

    const int nslab = (bj >> 1) + 1;      // k <= bj*32+31 (L triangular)

    for (int s = 0; s < nslab; ++s) {
        const int k0 = s * 64;
#pragma unroll
        for (int q = 0; q < 4; ++q) {
            float4 av = *(const float4*)&g_L[(size_t)(bi * 32 + lr) * NN + k0 + lc + 4 * q];
            float4 bv = *(const float4*)&g_L[(size_t)(bj * 32 + lr) * NN + k0 + lc + 4 * q];
            const int c = lc + 4 * q;
            As[c][lr] = av.x; As[c + 1][lr] = av.y; As[c + 2][lr] = av.z; As[c + 3][lr] = av.w;
            Bs[c][lr] = bv.x; Bs[c + 1][lr] = bv.y; Bs[c + 2][lr] = bv.z; Bs[c + 3][lr] = bv.w;
        }
        __syncthreads();

        const int kb = grp * 32;
#pragma unroll
        for (int kk = 0; kk < 32; ++kk) {
            float4 a = *(const float4*)&As[kb + kk][ty * 4];
            float4 bb = *(const float4*)&Bs[kb + kk][tx * 4];
            acc[0][0] += a.x * bb.x; acc[0][1] += a.x * bb.y; acc[0][2] += a.x * bb.z; acc[0][3] += a.x * bb.w;
            acc[1][0] += a.y * bb.x; acc[1][1] += a.y * bb.y; acc[1][2] += a.y * bb.z; acc[1][3] += a.y * bb.w;
            acc[2][0] += a.z * bb.x; acc[2][1] += a.z * bb.y; acc[2][2] += a.z * bb.z; acc[2][3] += a.z * bb.w;
            acc[3][0] += a.w * bb.x; acc[3][1] += a.w * bb.y; acc[3][2] += a.w * bb.z; acc[3][3] += a.w * bb.w;
        }
        __syncthreads();
    }

    if (grp == 1) {
#pragma unroll
        for (int i = 0; i < 4; ++i)
#pragma unroll
            for (int j = 0; j < 4; ++j) red[id64][i * 4 + j] = acc[i][j];
    }
    __syncthreads();
    if (grp == 0) {
#pragma unroll
        for (int i = 0; i < 4; ++i)
#pragma unroll
            for (int j = 0; j < 4; ++j) acc[i][j] += red[id64][i * 4 + j];

        const int R = bi * 32 + ty * 4;
        const int C = bj * 32 + tx * 4;
#pragma unroll
        for (int i = 0; i < 4; ++i) {
            float4 v; v.x = acc[i][0]; v.y = acc[i][1]; v.z = acc[i][2]; v.w = acc[i][3];
            *(float4*)&D[(size_t)(R + i) * NN + C] = v;
        }
        if (bi != bj) {   // mirror (D symmetric)
#pragma unroll
            for (int j = 0; j < 4; ++j) {
                float4 v; v.x = acc[0][j]; v.y = acc[1][j]; v.z = acc[2][j]; v.w = acc[3][j];
                *(float4*)&D[(size_t)(C + j) * NN + R] = v;
            }
        }
    }
}

// ---------------------------------------------------------------------------
extern "C" void kernel_launch(void* const* d_in, const int* in_sizes, int n_in,
                              void* d_out, int out_size) {
    const float* input = (const float*)d_in[0];
    const float* W0    = (const float*)d_in[1];
    const float* b0    = (const float*)d_in[2];
    const float* W1    = (const float*)d_in[3];
    const float* b1    = (const float*)d_in[4];
    const float* W2    = (const float*)d_in[5];
    const float* b2    = (const float*)d_in[6];
    const float* Wo    = (const float*)d_in[7];
    const float* bo    = (const float*)d_in[8];
    float* out = (float*)d_out;

    // Fused 3-layer MLP (single launch, coalesced split-i, grid barriers)
    mlp_all<<<MB, 256>>>(input, W0, b0, W1, b1, W2);

    // Dominant GEMV over Wo (537 MB stream); fuses tanh(b2 + partials)
    dim3 gv((OUT4 + 255) / 256, SPLITK);
    gemv_out<<<gv, 256>>>(Wo, b2);

    // Fused L assembly + D = L L^T (lower-triangle blocks only)
    buildL_gemm<<<GB, 128>>>(bo, out);
}